// round 13
// baseline (speedup 1.0000x reference)
#include <cuda_runtime.h>
#include <cuda_fp16.h>
#include <mma.h>
#include <cstdint>

using namespace nvcuda;

#define KPOLY 3
#define NN 10000
#define KCH 32
#define MTILE 256
#define MTG ((NN + MTILE - 1) / MTILE)  // 40
#define SPLITS 12            // 3 polys x 4 K-quarters (round-10 proven)
#define KSPL 2560            // last split 2320
#define PKE ((size_t)NN * NN)           // elems per poly k (1e8)
#define SCALE 8192.0f
#define INV_SCALE (1.0f / 8192.0f)

// ---------------- scratch (static device arrays; no allocation) ----------------
__device__ __align__(16) half g_T1[(size_t)64 * KPOLY * NN];   // T1^T fp16 [c][k][n]
__device__ __align__(16) half g_T2[(size_t)32 * KPOLY * NN];
__device__ __align__(16) half g_Af[(size_t)KPOLY * PKE];       // poly * SCALE, fp16
__device__ float g_P1[(size_t)SPLITS * NN * 64];
__device__ float g_P2[(size_t)SPLITS * NN * 32];
__device__ __align__(16) float g_X1[(size_t)NN * 64];          // relu(sum P1)/S

__device__ __forceinline__ uint32_t smem_u32(const void* p) {
    uint32_t a;
    asm("{ .reg .u64 t; cvta.to.shared.u64 t, %1; cvt.u32.u64 %0, t; }" : "=r"(a) : "l"(p));
    return a;
}

#define CP_ASYNC(dst, src, pb) \
    asm volatile("cp.async.cg.shared.global [%0], [%1], 16, %2;" \
        :: "r"(dst), "l"(src), "r"(pb) : "memory")
#define CP_COMMIT() asm volatile("cp.async.commit_group;" ::: "memory")
#define CP_WAIT1()  asm volatile("cp.async.wait_group 1;" ::: "memory")
#define CP_WAIT2()  asm volatile("cp.async.wait_group 2;" ::: "memory")

// =======================================================================
// presplit (per poly k): fp32 -> fp16*SCALE. Pure streaming, 600 MB.
// =======================================================================
__global__ void __launch_bounds__(256)
presplit_kernel(const float* __restrict__ polyk, half* __restrict__ Afk) {
    const size_t base = ((size_t)blockIdx.x * 256 + threadIdx.x) * 16;
    if (base >= PKE) return;
    const float4* src = (const float4*)(polyk + base);
    uint32_t h[8];
#pragma unroll
    for (int j = 0; j < 4; j++) {
        float4 v = src[j];
        __half2 a = __floats2half2_rn(v.x * SCALE, v.y * SCALE);
        __half2 b = __floats2half2_rn(v.z * SCALE, v.w * SCALE);
        h[2 * j]     = *(const uint32_t*)&a;
        h[2 * j + 1] = *(const uint32_t*)&b;
    }
    uint4* d = (uint4*)(Afk + base);
    d[0] = make_uint4(h[0], h[1], h[2], h[3]);
    d[1] = make_uint4(h[4], h[5], h[6], h[7]);
}

// =======================================================================
// poly MMA kernel: single-pass fp16 (round-10 proven core).
// split = kbase + blockIdx.y; k = split>>2; K-slice (split&3)*KSPL.
// =======================================================================
template <int C, int STG, int NCTA>
__global__ void __launch_bounds__(256, NCTA)
poly_mma_kernel(const half* __restrict__ Bg,
                const half* __restrict__ Ag,
                float* __restrict__ P,
                int kbase) {
    constexpr int LDA = 40, LDB = 40;
    constexpr int APL = MTILE * LDA * 2;   // 20480
    constexpr int BPL = C * LDB * 2;       // 5120 / 2560
    constexpr int SS = APL + BPL;
    constexpr int NT = C / 16;
    extern __shared__ __align__(128) char smem[];
    const uint32_t sb = smem_u32(smem);

    const int tid = threadIdx.x;
    const int warp = tid >> 5;
    const int split = kbase + blockIdx.y;
    const int k = split >> 2;
    const int mbase = (split & 3) * KSPL;
    const int klen = min(NN - mbase, KSPL);
    const int nch = (klen + KCH - 1) / KCH;
    const int row0 = blockIdx.x * MTILE;

    // ---- B cp.async: plane C x 32 halves per chunk ----
    const int bc = tid >> 2, bk8 = (tid & 3) * 8;
    const half* bsrc = Bg + ((size_t)bc * KPOLY + k) * NN + mbase + bk8;
    const uint32_t bdoff = (uint32_t)(APL + (bc * LDB + bk8) * 2);
    auto issueB = [&](int ch) {
        if (C == 64 || tid < 128) {
            const int mc = ch * KCH;
            const int kv = klen - mc;
            const int pb = (bk8 < kv) ? 16 : 0;
            CP_ASYNC(sb + (ch % STG) * SS + bdoff, pb ? (bsrc + mc) : bsrc, pb);
        }
    };

    // ---- A cp.async: rows ar+64j (j=0..3), cols ak8..+7 ----
    const int ar = tid >> 2, ak8 = (tid & 3) * 8;
    const half* asrc[4];
    uint32_t adoff[4];
#pragma unroll
    for (int j = 0; j < 4; j++) {
        const int r = ar + j * 64;
        const int arow = min(row0 + r, NN - 1);  // clamp; rows discarded at store
        asrc[j] = Ag + ((size_t)k * NN + arow) * NN + mbase + ak8;
        adoff[j] = (uint32_t)((r * LDA + ak8) * 2);
    }
    auto issueA = [&](int ch) {
        const int mc = ch * KCH;
        const int kv = klen - mc;
        const int pb = (ak8 < kv) ? 16 : 0;
        const uint32_t base = sb + (ch % STG) * SS;
#pragma unroll
        for (int j = 0; j < 4; j++)
            CP_ASYNC(base + adoff[j], pb ? (asrc[j] + mc) : asrc[j], pb);
    };

    // ---- accumulators: 2 row-frags x NT ----
    wmma::fragment<wmma::accumulator, 16, 16, 16, float> acc[2][NT];
#pragma unroll
    for (int r = 0; r < 2; r++)
#pragma unroll
        for (int n = 0; n < NT; n++) wmma::fill_fragment(acc[r][n], 0.0f);

    auto domma = [&](int ch) {
        const half* Ap = (const half*)(smem + (ch % STG) * SS);
        const half* Bp = (const half*)(smem + (ch % STG) * SS + APL);
        const int wr = warp * 32;
#pragma unroll
        for (int ks = 0; ks < 2; ks++) {
            wmma::fragment<wmma::matrix_a, 16, 16, 16, half, wmma::row_major> fa[2];
#pragma unroll
            for (int r = 0; r < 2; r++)
                wmma::load_matrix_sync(fa[r], Ap + (wr + r * 16) * LDA + ks * 16, LDA);
#pragma unroll
            for (int n = 0; n < NT; n++) {
                wmma::fragment<wmma::matrix_b, 16, 16, 16, half, wmma::col_major> fb;
                wmma::load_matrix_sync(fb, Bp + n * 16 * LDB + ks * 16, LDB);
                wmma::mma_sync(acc[0][n], fa[0], fb, acc[0][n]);
                wmma::mma_sync(acc[1][n], fa[1], fb, acc[1][n]);
            }
        }
    };

    // ---- pipeline ----
#pragma unroll
    for (int i = 0; i < STG - 1; i++) { issueA(i); issueB(i); CP_COMMIT(); }
    for (int ch = 0; ch < nch; ch++) {
        if (STG == 4) CP_WAIT2(); else CP_WAIT1();
        __syncthreads();
        issueA(ch + STG - 1); issueB(ch + STG - 1); CP_COMMIT();
        domma(ch);
    }

    // ---- store partials ----
#pragma unroll
    for (int r = 0; r < 2; r++) {
        const int nrow = row0 + warp * 32 + r * 16;
        if (nrow < NN) {
            float* o = P + ((size_t)split * NN + nrow) * C;
#pragma unroll
            for (int n = 0; n < NT; n++)
                wmma::store_matrix_sync(o + n * 16, acc[r][n], C, wmma::mem_row_major);
        }
    }
}

// =======================================================================
// reduce+relu: X1 = relu(sum_s P1[s]) / SCALE. Pure streaming.
// =======================================================================
__global__ void __launch_bounds__(256)
reduce_relu_kernel(float* __restrict__ X1) {
    int i = blockIdx.x * blockDim.x + threadIdx.x;
    if (i < NN * 64 / 4) {
        float4 acc = make_float4(0.f, 0.f, 0.f, 0.f);
#pragma unroll
        for (int s = 0; s < SPLITS; s++) {
            float4 v = *(const float4*)(g_P1 + (size_t)s * NN * 64 + (size_t)i * 4);
            acc.x += v.x; acc.y += v.y; acc.z += v.z; acc.w += v.w;
        }
        acc.x = fmaxf(acc.x, 0.f) * INV_SCALE;
        acc.y = fmaxf(acc.y, 0.f) * INV_SCALE;
        acc.z = fmaxf(acc.z, 0.f) * INV_SCALE;
        acc.w = fmaxf(acc.w, 0.f) * INV_SCALE;
        *(float4*)(X1 + (size_t)i * 4) = acc;
    }
}

// =======================================================================
// Small GEMM: Tt[c][k][n] = (X @ W[k])[n][c] as fp16.
// =======================================================================
template <int DOUT>
__global__ void __launch_bounds__(256)
gemm_xw_kernel(const float* __restrict__ X, const float* __restrict__ W,
               half* __restrict__ T) {
    constexpr int DIN = 64;
    constexpr int MR = 256 / (DOUT / 8);
    __shared__ float Ws[DIN * DOUT];
    __shared__ float Xs[MR * (DIN + 1)];
    const int tid = threadIdx.x;
    const int kb = blockIdx.y;
    const int m0 = blockIdx.x * MR;

    for (int i = tid; i < DIN * DOUT; i += 256)
        Ws[i] = W[(size_t)kb * DIN * DOUT + i];
    for (int i = tid; i < MR * DIN; i += 256) {
        int r = i >> 6, d = i & 63;
        int n = m0 + r;
        if (n > NN - 1) n = NN - 1;
        Xs[r * (DIN + 1) + d] = X[(size_t)n * DIN + d];
    }
    __syncthreads();

    const int row = tid % MR;
    const int c0 = (tid / MR) * 8;
    float a[8];
#pragma unroll
    for (int c = 0; c < 8; c++) a[c] = 0.f;
#pragma unroll
    for (int d = 0; d < DIN; d++) {
        float xv = Xs[row * (DIN + 1) + d];
        float4 wa = *(const float4*)&Ws[d * DOUT + c0];
        float4 wb = *(const float4*)&Ws[d * DOUT + c0 + 4];
        a[0] = fmaf(xv, wa.x, a[0]); a[1] = fmaf(xv, wa.y, a[1]);
        a[2] = fmaf(xv, wa.z, a[2]); a[3] = fmaf(xv, wa.w, a[3]);
        a[4] = fmaf(xv, wb.x, a[4]); a[5] = fmaf(xv, wb.y, a[5]);
        a[6] = fmaf(xv, wb.z, a[6]); a[7] = fmaf(xv, wb.w, a[7]);
    }
    const int n = m0 + row;
    if (n < NN) {
#pragma unroll
        for (int c = 0; c < 8; c++)
            T[((size_t)(c0 + c) * KPOLY + kb) * NN + n] = __float2half_rn(a[c]);
    }
}

// Final reduction of layer-2 partials into d_out
__global__ void __launch_bounds__(256)
reduce_out_kernel(float* __restrict__ out) {
    int i = blockIdx.x * blockDim.x + threadIdx.x;
    if (i < NN * 32 / 4) {
        float4 acc = make_float4(0.f, 0.f, 0.f, 0.f);
#pragma unroll
        for (int s = 0; s < SPLITS; s++) {
            float4 v = *(const float4*)(g_P2 + (size_t)s * NN * 32 + (size_t)i * 4);
            acc.x += v.x; acc.y += v.y; acc.z += v.z; acc.w += v.w;
        }
        acc.x *= INV_SCALE; acc.y *= INV_SCALE; acc.z *= INV_SCALE; acc.w *= INV_SCALE;
        *(float4*)(out + (size_t)i * 4) = acc;
    }
}

extern "C" void kernel_launch(void* const* d_in, const int* in_sizes, int n_in,
                              void* d_out, int out_size) {
    const float* x    = (const float*)d_in[0];
    const float* poly = (const float*)d_in[1];
    const float* W1   = (const float*)d_in[2];
    const float* W2   = (const float*)d_in[3];
    float* out = (float*)d_out;

    constexpr int SS64 = MTILE * 40 * 2 + 64 * 40 * 2;  // 25600
    constexpr int SS32 = MTILE * 40 * 2 + 32 * 40 * 2;  // 23040
    constexpr int SMEM64 = 4 * SS64;  // 102400 (4-stage, 2 CTAs/SM)
    constexpr int SMEM32 = 3 * SS32;  // 69120  (3-stage, 3 CTAs/SM)

    // One-time resource setup (attrs + side stream + events).
    static cudaStream_t s1 = nullptr;
    static cudaEvent_t eFork = nullptr, ePs[KPOLY] = {nullptr, nullptr, nullptr};
    if (!s1) {
        cudaFuncSetAttribute((const void*)poly_mma_kernel<64, 4, 2>,
                             cudaFuncAttributeMaxDynamicSharedMemorySize, SMEM64);
        cudaFuncSetAttribute((const void*)poly_mma_kernel<32, 3, 3>,
                             cudaFuncAttributeMaxDynamicSharedMemorySize, SMEM32);
        cudaStreamCreateWithFlags(&s1, cudaStreamNonBlocking);
        cudaEventCreateWithFlags(&eFork, cudaEventDisableTiming);
        for (int k = 0; k < KPOLY; k++)
            cudaEventCreateWithFlags(&ePs[k], cudaEventDisableTiming);
    }

    half *T1, *T2, *Af;
    float *P1, *P2, *X1;
    cudaGetSymbolAddress((void**)&T1, g_T1);
    cudaGetSymbolAddress((void**)&T2, g_T2);
    cudaGetSymbolAddress((void**)&Af, g_Af);
    cudaGetSymbolAddress((void**)&P1, g_P1);
    cudaGetSymbolAddress((void**)&P2, g_P2);
    cudaGetSymbolAddress((void**)&X1, g_X1);

    dim3 g1((NN + 31) / 32, KPOLY);
    dim3 g2((NN + 63) / 64, KPOLY);
    dim3 gp1k(MTG, 4);        // one poly k: 4 K-quarter splits
    dim3 gp2(MTG, SPLITS);
    const int psBlocks = (int)((PKE / 16 + 255) / 256);

    // Fork: presplit per-k on side stream.
    cudaEventRecord(eFork, 0);
    cudaStreamWaitEvent(s1, eFork, 0);
    for (int k = 0; k < KPOLY; k++) {
        presplit_kernel<<<psBlocks, 256, 0, s1>>>(poly + (size_t)k * PKE,
                                                  Af + (size_t)k * PKE);
        cudaEventRecord(ePs[k], s1);
    }

    // Main stream: gemm64 runs concurrently with presplit(k0).
    gemm_xw_kernel<64><<<g1, 256>>>(x, W1, T1);
    for (int k = 0; k < KPOLY; k++) {
        cudaStreamWaitEvent(0, ePs[k], 0);   // join per-k (k=2 joins s1 fully)
        poly_mma_kernel<64, 4, 2><<<gp1k, 256, SMEM64>>>(T1, Af, P1, k * 4);
    }
    reduce_relu_kernel<<<(NN * 64 / 4 + 255) / 256, 256>>>(X1);
    gemm_xw_kernel<32><<<g2, 256>>>(X1, W2, T2);
    poly_mma_kernel<32, 3, 3><<<gp2, 256, SMEM32>>>(T2, Af, P2, 0);
    reduce_out_kernel<<<(NN * 32 / 4 + 255) / 256, 256>>>(out);
}

// round 14
// speedup vs baseline: 1.1736x; 1.1736x over previous
#include <cuda_runtime.h>
#include <cuda_fp16.h>
#include <mma.h>
#include <cstdint>

using namespace nvcuda;

#define KPOLY 3
#define NN 10000
#define KCH 32
#define MTILE 256
#define MTG ((NN + MTILE - 1) / MTILE)  // 40
#define SPLITS 12            // 3 polys x 4 K-quarters (round-10 proven)
#define KSPL 2560            // last split 2320
#define TOTE ((size_t)KPOLY * NN * NN)
#define SCALE 8192.0f
#define INV_SCALE (1.0f / 8192.0f)

// ---------------- scratch (static device arrays; no allocation) ----------------
__device__ __align__(16) half g_T1[(size_t)64 * KPOLY * NN];   // T1^T fp16 [c][k][n]
__device__ __align__(16) half g_T2[(size_t)32 * KPOLY * NN];
__device__ __align__(16) half g_Af[TOTE];                      // poly * SCALE, fp16
__device__ float g_P1[(size_t)SPLITS * NN * 64];
__device__ float g_P2[(size_t)SPLITS * NN * 32];
__device__ __align__(16) float g_X1[(size_t)NN * 64];          // relu(sum P1)/S

__device__ __forceinline__ uint32_t smem_u32(const void* p) {
    uint32_t a;
    asm("{ .reg .u64 t; cvta.to.shared.u64 t, %1; cvt.u32.u64 %0, t; }" : "=r"(a) : "l"(p));
    return a;
}

#define CP_ASYNC(dst, src, pb) \
    asm volatile("cp.async.cg.shared.global [%0], [%1], 16, %2;" \
        :: "r"(dst), "l"(src), "r"(pb) : "memory")
#define CP_COMMIT() asm volatile("cp.async.commit_group;" ::: "memory")
#define CP_WAIT1()  asm volatile("cp.async.wait_group 1;" ::: "memory")
#define CP_WAIT2()  asm volatile("cp.async.wait_group 2;" ::: "memory")

// =======================================================================
// presplit: poly fp32 -> fp16*SCALE. Pure streaming, 1.8 GB.
// =======================================================================
__global__ void __launch_bounds__(256)
presplit_kernel(const float* __restrict__ poly, half* __restrict__ Af) {
    const size_t base = ((size_t)blockIdx.x * 256 + threadIdx.x) * 16;
    if (base >= TOTE) return;
    const float4* src = (const float4*)(poly + base);
    uint32_t h[8];
#pragma unroll
    for (int j = 0; j < 4; j++) {
        float4 v = src[j];
        __half2 a = __floats2half2_rn(v.x * SCALE, v.y * SCALE);
        __half2 b = __floats2half2_rn(v.z * SCALE, v.w * SCALE);
        h[2 * j]     = *(const uint32_t*)&a;
        h[2 * j + 1] = *(const uint32_t*)&b;
    }
    uint4* d = (uint4*)(Af + base);
    d[0] = make_uint4(h[0], h[1], h[2], h[3]);
    d[1] = make_uint4(h[4], h[5], h[6], h[7]);
}

// =======================================================================
// poly MMA kernel: single-pass fp16 (round-10 proven core).
// MTILE=256, 8 warps x 32 rows (2 row-frags), KCH=32, STG-stage pipeline.
// LDA=LDB=40 halves (80B stride: conflict-free ldmatrix, 16B aligned).
// =======================================================================
template <int C, int STG, int NCTA>
__global__ void __launch_bounds__(256, NCTA)
poly_mma_kernel(const half* __restrict__ Bg,
                const half* __restrict__ Ag,
                float* __restrict__ P) {
    constexpr int LDA = 40, LDB = 40;
    constexpr int APL = MTILE * LDA * 2;   // 20480
    constexpr int BPL = C * LDB * 2;       // 5120 / 2560
    constexpr int SS = APL + BPL;
    constexpr int NT = C / 16;
    extern __shared__ __align__(128) char smem[];
    const uint32_t sb = smem_u32(smem);

    const int tid = threadIdx.x;
    const int warp = tid >> 5;
    const int split = blockIdx.y;
    const int k = split >> 2;
    const int mbase = (split & 3) * KSPL;
    const int klen = min(NN - mbase, KSPL);
    const int nch = (klen + KCH - 1) / KCH;
    const int row0 = blockIdx.x * MTILE;

    // ---- B cp.async: plane C x 32 halves per chunk ----
    const int bc = tid >> 2, bk8 = (tid & 3) * 8;
    const half* bsrc = Bg + ((size_t)bc * KPOLY + k) * NN + mbase + bk8;
    const uint32_t bdoff = (uint32_t)(APL + (bc * LDB + bk8) * 2);
    auto issueB = [&](int ch) {
        if (C == 64 || tid < 128) {
            const int mc = ch * KCH;
            const int kv = klen - mc;
            const int pb = (bk8 < kv) ? 16 : 0;
            CP_ASYNC(sb + (ch % STG) * SS + bdoff, pb ? (bsrc + mc) : bsrc, pb);
        }
    };

    // ---- A cp.async: rows ar+64j (j=0..3), cols ak8..+7 ----
    const int ar = tid >> 2, ak8 = (tid & 3) * 8;
    const half* asrc[4];
    uint32_t adoff[4];
#pragma unroll
    for (int j = 0; j < 4; j++) {
        const int r = ar + j * 64;
        const int arow = min(row0 + r, NN - 1);  // clamp; rows discarded at store
        asrc[j] = Ag + ((size_t)k * NN + arow) * NN + mbase + ak8;
        adoff[j] = (uint32_t)((r * LDA + ak8) * 2);
    }
    auto issueA = [&](int ch) {
        const int mc = ch * KCH;
        const int kv = klen - mc;
        const int pb = (ak8 < kv) ? 16 : 0;
        const uint32_t base = sb + (ch % STG) * SS;
#pragma unroll
        for (int j = 0; j < 4; j++)
            CP_ASYNC(base + adoff[j], pb ? (asrc[j] + mc) : asrc[j], pb);
    };

    // ---- accumulators: 2 row-frags x NT ----
    wmma::fragment<wmma::accumulator, 16, 16, 16, float> acc[2][NT];
#pragma unroll
    for (int r = 0; r < 2; r++)
#pragma unroll
        for (int n = 0; n < NT; n++) wmma::fill_fragment(acc[r][n], 0.0f);

    auto domma = [&](int ch) {
        const half* Ap = (const half*)(smem + (ch % STG) * SS);
        const half* Bp = (const half*)(smem + (ch % STG) * SS + APL);
        const int wr = warp * 32;
#pragma unroll
        for (int ks = 0; ks < 2; ks++) {
            wmma::fragment<wmma::matrix_a, 16, 16, 16, half, wmma::row_major> fa[2];
#pragma unroll
            for (int r = 0; r < 2; r++)
                wmma::load_matrix_sync(fa[r], Ap + (wr + r * 16) * LDA + ks * 16, LDA);
#pragma unroll
            for (int n = 0; n < NT; n++) {
                wmma::fragment<wmma::matrix_b, 16, 16, 16, half, wmma::col_major> fb;
                wmma::load_matrix_sync(fb, Bp + n * 16 * LDB + ks * 16, LDB);
                wmma::mma_sync(acc[0][n], fa[0], fb, acc[0][n]);
                wmma::mma_sync(acc[1][n], fa[1], fb, acc[1][n]);
            }
        }
    };

    // ---- pipeline: STG stages, STG-1 groups in flight ----
#pragma unroll
    for (int i = 0; i < STG - 1; i++) { issueA(i); issueB(i); CP_COMMIT(); }
    for (int ch = 0; ch < nch; ch++) {
        if (STG == 4) CP_WAIT2(); else CP_WAIT1();
        __syncthreads();
        issueA(ch + STG - 1); issueB(ch + STG - 1); CP_COMMIT();
        domma(ch);
    }

    // ---- store partials (16-row frag granularity; NN-9984=16 => frag-exact) ----
#pragma unroll
    for (int r = 0; r < 2; r++) {
        const int nrow = row0 + warp * 32 + r * 16;
        if (nrow < NN) {
            float* o = P + ((size_t)split * NN + nrow) * C;
#pragma unroll
            for (int n = 0; n < NT; n++)
                wmma::store_matrix_sync(o + n * 16, acc[r][n], C, wmma::mem_row_major);
        }
    }
}

// =======================================================================
// reduce+relu: X1 = relu(sum_s P1[s]) / SCALE. Pure streaming.
// =======================================================================
__global__ void __launch_bounds__(256)
reduce_relu_kernel(float* __restrict__ X1) {
    int i = blockIdx.x * blockDim.x + threadIdx.x;
    if (i < NN * 64 / 4) {
        float4 acc = make_float4(0.f, 0.f, 0.f, 0.f);
#pragma unroll
        for (int s = 0; s < SPLITS; s++) {
            float4 v = *(const float4*)(g_P1 + (size_t)s * NN * 64 + (size_t)i * 4);
            acc.x += v.x; acc.y += v.y; acc.z += v.z; acc.w += v.w;
        }
        acc.x = fmaxf(acc.x, 0.f) * INV_SCALE;
        acc.y = fmaxf(acc.y, 0.f) * INV_SCALE;
        acc.z = fmaxf(acc.z, 0.f) * INV_SCALE;
        acc.w = fmaxf(acc.w, 0.f) * INV_SCALE;
        *(float4*)(X1 + (size_t)i * 4) = acc;
    }
}

// =======================================================================
// Small GEMM: Tt[c][k][n] = (X @ W[k])[n][c] as fp16.
// Reg-capped: launch_bounds minBlocks=6 + bounded unroll (fixes regs=255).
// =======================================================================
template <int DOUT>
__global__ void __launch_bounds__(256, 6)
gemm_xw_kernel(const float* __restrict__ X, const float* __restrict__ W,
               half* __restrict__ T) {
    constexpr int DIN = 64;
    constexpr int MR = 256 / (DOUT / 8);
    __shared__ float Ws[DIN * DOUT];
    __shared__ float Xs[MR * (DIN + 1)];
    const int tid = threadIdx.x;
    const int kb = blockIdx.y;
    const int m0 = blockIdx.x * MR;

    for (int i = tid; i < DIN * DOUT; i += 256)
        Ws[i] = W[(size_t)kb * DIN * DOUT + i];
    for (int i = tid; i < MR * DIN; i += 256) {
        int r = i >> 6, d = i & 63;
        int n = m0 + r;
        if (n > NN - 1) n = NN - 1;
        Xs[r * (DIN + 1) + d] = X[(size_t)n * DIN + d];
    }
    __syncthreads();

    const int row = tid % MR;
    const int c0 = (tid / MR) * 8;
    float a[8];
#pragma unroll
    for (int c = 0; c < 8; c++) a[c] = 0.f;
#pragma unroll 16
    for (int d = 0; d < DIN; d++) {
        float xv = Xs[row * (DIN + 1) + d];
        float4 wa = *(const float4*)&Ws[d * DOUT + c0];
        float4 wb = *(const float4*)&Ws[d * DOUT + c0 + 4];
        a[0] = fmaf(xv, wa.x, a[0]); a[1] = fmaf(xv, wa.y, a[1]);
        a[2] = fmaf(xv, wa.z, a[2]); a[3] = fmaf(xv, wa.w, a[3]);
        a[4] = fmaf(xv, wb.x, a[4]); a[5] = fmaf(xv, wb.y, a[5]);
        a[6] = fmaf(xv, wb.z, a[6]); a[7] = fmaf(xv, wb.w, a[7]);
    }
    const int n = m0 + row;
    if (n < NN) {
#pragma unroll
        for (int c = 0; c < 8; c++)
            T[((size_t)(c0 + c) * KPOLY + kb) * NN + n] = __float2half_rn(a[c]);
    }
}

// Final reduction of layer-2 partials into d_out
__global__ void __launch_bounds__(256)
reduce_out_kernel(float* __restrict__ out) {
    int i = blockIdx.x * blockDim.x + threadIdx.x;
    if (i < NN * 32 / 4) {
        float4 acc = make_float4(0.f, 0.f, 0.f, 0.f);
#pragma unroll
        for (int s = 0; s < SPLITS; s++) {
            float4 v = *(const float4*)(g_P2 + (size_t)s * NN * 32 + (size_t)i * 4);
            acc.x += v.x; acc.y += v.y; acc.z += v.z; acc.w += v.w;
        }
        acc.x *= INV_SCALE; acc.y *= INV_SCALE; acc.z *= INV_SCALE; acc.w *= INV_SCALE;
        *(float4*)(out + (size_t)i * 4) = acc;
    }
}

extern "C" void kernel_launch(void* const* d_in, const int* in_sizes, int n_in,
                              void* d_out, int out_size) {
    const float* x    = (const float*)d_in[0];
    const float* poly = (const float*)d_in[1];
    const float* W1   = (const float*)d_in[2];
    const float* W2   = (const float*)d_in[3];
    float* out = (float*)d_out;

    constexpr int SS64 = MTILE * 40 * 2 + 64 * 40 * 2;  // 25600
    constexpr int SS32 = MTILE * 40 * 2 + 32 * 40 * 2;  // 23040
    constexpr int SMEM64 = 4 * SS64;  // 102400 (4-stage, 2 CTAs/SM)
    constexpr int SMEM32 = 3 * SS32;  // 69120  (3-stage, 3 CTAs/SM)

    // One-time resource setup (attrs + side stream + events).
    static cudaStream_t s1 = nullptr;
    static cudaEvent_t eFork = nullptr, ePs = nullptr;
    if (!s1) {
        cudaFuncSetAttribute((const void*)poly_mma_kernel<64, 4, 2>,
                             cudaFuncAttributeMaxDynamicSharedMemorySize, SMEM64);
        cudaFuncSetAttribute((const void*)poly_mma_kernel<32, 3, 3>,
                             cudaFuncAttributeMaxDynamicSharedMemorySize, SMEM32);
        cudaStreamCreateWithFlags(&s1, cudaStreamNonBlocking);
        cudaEventCreateWithFlags(&eFork, cudaEventDisableTiming);
        cudaEventCreateWithFlags(&ePs, cudaEventDisableTiming);
    }

    half *T1, *T2, *Af;
    float *P1, *P2, *X1;
    cudaGetSymbolAddress((void**)&T1, g_T1);
    cudaGetSymbolAddress((void**)&T2, g_T2);
    cudaGetSymbolAddress((void**)&Af, g_Af);
    cudaGetSymbolAddress((void**)&P1, g_P1);
    cudaGetSymbolAddress((void**)&P2, g_P2);
    cudaGetSymbolAddress((void**)&X1, g_X1);

    dim3 g1((NN + 31) / 32, KPOLY);
    dim3 g2((NN + 63) / 64, KPOLY);
    dim3 gp(MTG, SPLITS);
    const int psBlocks = (int)((TOTE / 16 + 255) / 256);

    // Fork: presplit (whole tensor, one launch) on side stream;
    // gemm64 (independent inputs) runs concurrently on main stream.
    cudaEventRecord(eFork, 0);
    cudaStreamWaitEvent(s1, eFork, 0);
    presplit_kernel<<<psBlocks, 256, 0, s1>>>(poly, Af);
    cudaEventRecord(ePs, s1);

    gemm_xw_kernel<64><<<g1, 256>>>(x, W1, T1);
    cudaStreamWaitEvent(0, ePs, 0);   // join: poly1 needs full Af

    poly_mma_kernel<64, 4, 2><<<gp, 256, SMEM64>>>(T1, Af, P1);
    reduce_relu_kernel<<<(NN * 64 / 4 + 255) / 256, 256>>>(X1);
    gemm_xw_kernel<32><<<g2, 256>>>(X1, W2, T2);
    poly_mma_kernel<32, 3, 3><<<gp, 256, SMEM32>>>(T2, Af, P2);
    reduce_out_kernel<<<(NN * 32 / 4 + 255) / 256, 256>>>(out);
}